// round 7
// baseline (speedup 1.0000x reference)
#include <cuda_runtime.h>

// Problem constants (fixed by setup_inputs: H=480, W=1024, S=32, margin=10, step=4)
#define HH     480
#define WW     1024
#define SS     32
#define HWIMG  (HH*WW)          // 491520
#define NSLOT  61440            // 2*H*W/step^2
#define GXC    252
#define GYC    116
#define GG     (GXC*GYC)        // 29232
#define MARG   10
#define BB     240              // persistent grid: 240 blocks x 256 = NSLOT threads
#define TT     256
#define NWARP  (TT/32)
#define WPI    (HWIMG/32)       // 15360 bitmask words per step
#define NCHK   229              // 128-byte chunks covering GG
#define GPAD   (NCHK*128)       // 29312 (pad bytes kept = 1, never candidates)
#define NSUB   8
#define SUBQ   (BB/NSUB)        // 30

// Scratch (device globals; no allocations allowed)
// 3-buffer rotation: A(s) marks buf(s%3) & clears buf((s+1)%3); B'(s) reads buf(s%3).
// Every mark/clear/read pair is separated by a grid barrier (see region proof in analysis).
__device__ __align__(128) unsigned char g_occ3[3][GPAD];
__device__ unsigned g_on[(SS-1)*WPI];                 // precomputed fwd-bwd consistency bitmask
__device__ int g_slotCnt[2][BB];                      // parity double-buffered
struct __align__(128) PadCnt { unsigned v; unsigned pad[31]; };
__device__ PadCnt g_barSub[NSUB];
__device__ PadCnt g_barMaster;
__device__ __align__(128) volatile unsigned g_barGen;

__device__ __forceinline__ void gridbar() {
    __syncthreads();
    if (threadIdx.x == 0) {
        __threadfence();                       // release: publish this block's writes
        unsigned gen = g_barGen;               // read BEFORE arrival (else lost-release race)
        bool last = false;
        if (atomicAdd(&g_barSub[blockIdx.x & (NSUB - 1)].v, 1u) == SUBQ - 1u) {
            if (atomicAdd(&g_barMaster.v, 1u) == NSUB - 1u) last = true;
        }
        if (last) {
            g_barMaster.v = 0;
            #pragma unroll
            for (int i = 0; i < NSUB; i++) g_barSub[i].v = 0;
            __threadfence();
            g_barGen = gen + 1u;
        } else {
            while (g_barGen == gen) { }
        }
    }
    __syncthreads();
}

// ---- math helpers: byte-identical to R1..R6 (rel_err was 0.0) ----
__device__ __forceinline__ float bil4(float s00, float s01, float s10, float s11,
                                      float w00, float w01, float w10, float w11) {
    return fmaf(s11, w11, fmaf(s10, w10, fmaf(s00, w00, __fmul_rn(s01, w01))));
}

struct BilW {
    int ix0, ix1, iy0, iy1;
    float w00, w01, w10, w11;
};

__device__ __forceinline__ BilW mkw(float x, float y) {
    BilW b;
    float x0f = floorf(x), y0f = floorf(y);
    float wx1 = __fsub_rn(x, x0f); float wx0 = __fsub_rn(1.0f, wx1);
    float wy1 = __fsub_rn(y, y0f); float wy0 = __fsub_rn(1.0f, wy1);
    int ix0 = (int)x0f; ix0 = ix0 < 0 ? 0 : (ix0 > WW-1 ? WW-1 : ix0);
    int iy0 = (int)y0f; iy0 = iy0 < 0 ? 0 : (iy0 > HH-1 ? HH-1 : iy0);
    b.ix0 = ix0; b.ix1 = (ix0+1 > WW-1) ? WW-1 : ix0+1;
    b.iy0 = iy0; b.iy1 = (iy0+1 > HH-1) ? HH-1 : iy0+1;
    b.w00 = __fmul_rn(wy0, wx0); b.w01 = __fmul_rn(wy0, wx1);
    b.w10 = __fmul_rn(wy1, wx0); b.w11 = __fmul_rn(wy1, wx1);
    return b;
}

__device__ __forceinline__ float on_at(const float* __restrict__ fb0,
                                       const float* __restrict__ fb1,
                                       float a0, float a1, int py, int px) {
    float xt = __fadd_rn((float)px, a0);
    float yt = __fadd_rn((float)py, a1);
    BilW b = mkw(xt, yt);
    float f00 = fb0[b.iy0*WW+b.ix0], f01 = fb0[b.iy0*WW+b.ix1];
    float f10 = fb0[b.iy1*WW+b.ix0], f11 = fb0[b.iy1*WW+b.ix1];
    float g00 = fb1[b.iy0*WW+b.ix0], g01 = fb1[b.iy0*WW+b.ix1];
    float g10 = fb1[b.iy1*WW+b.ix0], g11 = fb1[b.iy1*WW+b.ix1];
    float f0 = bil4(f00, f01, f10, f11, b.w00, b.w01, b.w10, b.w11);
    float f1 = bil4(g00, g01, g10, g11, b.w00, b.w01, b.w10, b.w11);
    float d0 = __fadd_rn(a0, f0), d1 = __fadd_rn(a1, f1);
    float diff = __fsqrt_rn(fmaf(d1, d1, __fmul_rn(d0, d0)));
    float m1 = __fsqrt_rn(fmaf(a1, a1, __fmul_rn(a0, a0)));
    float m2 = __fsqrt_rn(fmaf(f1, f1, __fmul_rn(f0, f0)));
    float mag = __fmul_rn(0.5f, __fadd_rn(m1, m2));
    return (diff <= fmaf(0.01f, mag, 0.1f)) ? 1.0f : 0.0f;
}

// ---------------- precompute: dense fwd-bwd consistency bitmask, 4 px/thread ----------------
__global__ void __launch_bounds__(256) k_onmask(const float* __restrict__ ff,
                                                const float* __restrict__ fb) {
    int s = blockIdx.y;
    int t = blockIdx.x * 256 + threadIdx.x;
    int p = t * 4;                                 // base pixel (same row: p%1024 <= 1020)
    int lane = threadIdx.x & 31;
    const float* ff0 = ff + (size_t)s * 2 * HWIMG;
    const float* ff1 = ff0 + HWIMG;
    const float* fb0 = fb + (size_t)s * 2 * HWIMG;
    const float* fb1 = fb0 + HWIMG;
    float4 a = ((const float4*)ff0)[t];
    float4 c = ((const float4*)ff1)[t];
    int py = p >> 10;
    int px = p & 1023;
    float o0 = on_at(fb0, fb1, a.x, c.x, py, px);
    float o1 = on_at(fb0, fb1, a.y, c.y, py, px + 1);
    float o2 = on_at(fb0, fb1, a.z, c.z, py, px + 2);
    float o3 = on_at(fb0, fb1, a.w, c.w, py, px + 3);
    unsigned nib = (unsigned)(o0 != 0.0f) | ((unsigned)(o1 != 0.0f) << 1)
                 | ((unsigned)(o2 != 0.0f) << 2) | ((unsigned)(o3 != 0.0f) << 3);
    unsigned v = nib << ((lane & 7) * 4);
    v |= __shfl_xor_sync(0xffffffffu, v, 1);
    v |= __shfl_xor_sync(0xffffffffu, v, 2);
    v |= __shfl_xor_sync(0xffffffffu, v, 4);
    if ((lane & 7) == 0) g_on[s*WPI + (p >> 5)] = v;
}

// ---------------- persistent serial kernel, ONE grid barrier per step ----------------
__global__ void __launch_bounds__(TT, 2) k_linker(const float* __restrict__ ff,
                                                  float* __restrict__ out) {
    const int tid  = threadIdx.x;
    const int b    = blockIdx.x;
    const int lane = tid & 31;
    const int wid  = tid >> 5;
    const int t    = b * TT + tid;         // slot id

    float* X  = out;
    float* Y  = out + SS*NSLOT;
    float* St = out + 2*SS*NSLOT;

    __shared__ int sh_cnt, sh_slotBase, sh_nf, sh_nc;
    __shared__ int sh_w[NWARP], sh_wsum[NWARP], sh_woff[NWARP];
    __shared__ int sh_pre[TT];

    // ---- init: per-thread persistent state + occ pad bytes (occupied forever) ----
    float myX, myY, mySt;
    {
        bool ing = t < GG;
        myX  = ing ? (float)(MARG + 4*(t % GXC)) : 0.0f;
        myY  = ing ? (float)(MARG + 4*(t / GXC)) : 0.0f;
        mySt = ing ? 0.0f : -1.0f;
        X[t] = myX; Y[t] = myY;            // row 0
    }
    if (b == 0 && tid < GPAD - GG) {
        g_occ3[0][GG + tid] = 1; g_occ3[1][GG + tid] = 1; g_occ3[2][GG + tid] = 1;
    }

    for (int s = 0; s < SS - 1; s++) {
        unsigned char* bufm = g_occ3[s % 3];           // marked here, read in B'(s)
        unsigned char* bufc = g_occ3[(s + 1) % 3];     // cleared here (marked at A(s+1))
        const int par = s & 1;
        const float* ff0 = ff + (size_t)s * 2 * HWIMG;
        const float* ff1 = ff0 + HWIMG;
        const unsigned* onw = g_on + s*WPI;

        // ===== Phase A: clear next occ buffer (own cell), advance own slot, mark occ =====
        if (t < GG) bufc[t] = 0;

        bool freeflag = true;                 // == (updated Start < 0)
        float xw = 0.0f, yw = 0.0f;
        if (mySt >= 0.0f) {
            BilW bw = mkw(myX, myY);
            float u00 = ff0[bw.iy0*WW+bw.ix0], u01 = ff0[bw.iy0*WW+bw.ix1];
            float u10 = ff0[bw.iy1*WW+bw.ix0], u11 = ff0[bw.iy1*WW+bw.ix1];
            float v00 = ff1[bw.iy0*WW+bw.ix0], v01 = ff1[bw.iy0*WW+bw.ix1];
            float v10 = ff1[bw.iy1*WW+bw.ix0], v11 = ff1[bw.iy1*WW+bw.ix1];
            float uvx = bil4(u00, u01, u10, u11, bw.w00, bw.w01, bw.w10, bw.w11);
            float uvy = bil4(v00, v01, v10, v11, bw.w00, bw.w01, bw.w10, bw.w11);
            float xt = __fadd_rn(myX, uvx);
            float yt = __fadd_rn(myY, uvy);
            bool marg = (xt > (float)MARG) && (yt > (float)MARG) &&
                        (xt < (float)(WW - MARG)) && (yt < (float)(HH - MARG));
            if (marg) {
                // bitmask probes reconstruct exactly 0.0f/1.0f (bit-identical to on_at)
                float on00 = (float)((onw[(bw.iy0<<5) + (bw.ix0>>5)] >> (bw.ix0&31)) & 1u);
                float on01 = (float)((onw[(bw.iy0<<5) + (bw.ix1>>5)] >> (bw.ix1&31)) & 1u);
                float on10 = (float)((onw[(bw.iy1<<5) + (bw.ix0>>5)] >> (bw.ix0&31)) & 1u);
                float on11 = (float)((onw[(bw.iy1<<5) + (bw.ix1>>5)] >> (bw.ix1&31)) & 1u);
                float onv = bil4(on00, on01, on10, on11, bw.w00, bw.w01, bw.w10, bw.w11);
                if (onv > 0.5f) {
                    freeflag = false;
                    xw = xt; yw = yt;
                    int oy = (int)yt, ox = (int)xt;
                    int iylo = (oy - 9) / 4; if (iylo < 0) iylo = 0;
                    int iyhi = (oy - 8) / 4; if (iyhi > GYC-1) iyhi = GYC-1;
                    int ixlo = (ox - 9) / 4; if (ixlo < 0) ixlo = 0;
                    int ixhi = (ox - 8) / 4; if (ixhi > GXC-1) ixhi = GXC-1;
                    for (int iy = iylo; iy <= iyhi; iy++)
                        for (int ix = ixlo; ix <= ixhi; ix++)
                            bufm[iy*GXC + ix] = 1;         // idempotent
                }
            }
        }
        if (freeflag) mySt = -1.0f;
        myX = xw; myY = yw;
        X[(s+1)*NSLOT + t] = xw;
        Y[(s+1)*NSLOT + t] = yw;

        if (tid == 0) sh_cnt = 0;
        __syncthreads();
        unsigned amask = __ballot_sync(0xffffffffu, freeflag);
        if (lane == 0) atomicAdd(&sh_cnt, __popc(amask));
        __syncthreads();
        if (tid == 0) g_slotCnt[par][b] = sh_cnt;

        gridbar();   // occ marks + slot counts + row s+1 visible

        // ===== Phase B': rank free slots, scan full occ, self-birth =====
        if (tid == 0) { sh_slotBase = 0; sh_nf = 0; }
        __syncthreads();
        {
            // full-warp collectives (no partial-warp entry)
            int c = (tid < BB) ? __ldcg(&g_slotCnt[par][tid]) : 0;
            int tot = __reduce_add_sync(0xffffffffu, c);
            int pre = __reduce_add_sync(0xffffffffu, (tid < b) ? c : 0);
            if (lane == 0) {
                atomicAdd(&sh_nf, tot);
                if (pre) atomicAdd(&sh_slotBase, pre);
            }
        }
        unsigned smask = __ballot_sync(0xffffffffu, freeflag);
        if (lane == 0) sh_w[wid] = __popc(smask);

        // per-chunk zero counts over the FULL occ map (balanced across blocks)
        const unsigned char* occ = bufm;
        int cnt = 0;
        if (tid < NCHK) {
            const uint4* cp = (const uint4*)(occ + tid * 128);
            #pragma unroll
            for (int w = 0; w < 8; w++) {
                uint4 v = __ldcg(cp + w);
                cnt += __popc(__vcmpeq4(v.x, 0u)) + __popc(__vcmpeq4(v.y, 0u))
                     + __popc(__vcmpeq4(v.z, 0u)) + __popc(__vcmpeq4(v.w, 0u));
            }
            cnt >>= 3;                                 // bytes, not bits
        }
        // block exclusive scan of chunk counts
        int inc = cnt;
        #pragma unroll
        for (int d = 1; d < 32; d <<= 1) {
            int n = __shfl_up_sync(0xffffffffu, inc, d);
            if (lane >= d) inc += n;
        }
        if (lane == 31) sh_wsum[wid] = inc;
        __syncthreads();
        if (tid == 0) {
            int run0 = sh_slotBase;
            #pragma unroll
            for (int i = 0; i < NWARP; i++) { int c2 = sh_w[i]; sh_w[i] = run0; run0 += c2; }
            int run1 = 0;
            #pragma unroll
            for (int i = 0; i < NWARP; i++) { int c2 = sh_wsum[i]; sh_woff[i] = run1; run1 += c2; }
            sh_nc = run1;                              // total free candidates (deterministic)
        }
        __syncthreads();
        sh_pre[tid] = sh_woff[wid] + inc - cnt;        // exclusive chunk prefix
        int myrank = freeflag ? sh_w[wid] + __popc(smask & ((1u << lane) - 1u)) : -1;
        int nf = sh_nf;
        int nc = sh_nc;
        __syncthreads();

        // self-birth: k-th free slot takes k-th free candidate (= k-th zero byte of occ)
        int m = nf < nc ? nf : nc;
        if (myrank >= 0 && myrank < m) {
            int r = myrank;
            int lo = 0, hi = NCHK - 1;
            while (lo < hi) {                          // last chunk with prefix <= r
                int mid = (lo + hi + 1) >> 1;
                if (sh_pre[mid] <= r) lo = mid; else hi = mid - 1;
            }
            int k = r - sh_pre[lo];
            const uint4* cp = (const uint4*)(occ + lo * 128);
            int g = -1, cum = 0;
            for (int w = 0; w < 8 && g < 0; w++) {
                uint4 v = __ldcg(cp + w);
                unsigned zb[4] = { __vcmpeq4(v.x, 0u), __vcmpeq4(v.y, 0u),
                                   __vcmpeq4(v.z, 0u), __vcmpeq4(v.w, 0u) };
                int z16 = (__popc(zb[0]) + __popc(zb[1]) + __popc(zb[2]) + __popc(zb[3])) >> 3;
                if (cum + z16 <= k) { cum += z16; continue; }
                for (int j = 0; j < 4 && g < 0; j++) {
                    int zw = __popc(zb[j]) >> 3;
                    if (cum + zw <= k) { cum += zw; continue; }
                    unsigned zm = zb[j];
                    for (int l = 0; l < 4; l++) {
                        if ((zm >> (8 * l)) & 0xFFu) {
                            if (cum == k) { g = lo * 128 + w * 16 + j * 4 + l; break; }
                            cum++;
                        }
                    }
                }
            }
            int iy = g / GXC, ix = g - iy * GXC;
            myX = (float)(MARG + 4*ix);
            myY = (float)(MARG + 4*iy);
            mySt = (float)(s + 1);
            X[(s+1)*NSLOT + t] = myX;
            Y[(s+1)*NSLOT + t] = myY;
        }
        // no trailing barrier: next Phase A touches buf((s+1)%3) (cleared, barrier-separated)
        // and thread-own state only.
    }

    St[t] = mySt;
    gridbar();   // all B'(30) reads of buf0 complete
    if (t < GG) { g_occ3[0][t] = 0; g_occ3[2][t] = 0; }   // restore zero-invariant (buf1 clean)
}

extern "C" void kernel_launch(void* const* d_in, const int* in_sizes, int n_in,
                              void* d_out, int out_size) {
    (void)in_sizes; (void)n_in; (void)out_size;
    const float* ff = (const float*)d_in[0];
    const float* fb = (const float*)d_in[1];
    float* out = (float*)d_out;
    dim3 g1(HWIMG/1024, SS-1);
    k_onmask<<<g1, 256>>>(ff, fb);
    k_linker<<<BB, TT>>>(ff, out);
}

// round 8
// speedup vs baseline: 1.7000x; 1.7000x over previous
#include <cuda_runtime.h>

// Problem constants (fixed by setup_inputs: H=480, W=1024, S=32, margin=10, step=4)
#define HH     480
#define WW     1024
#define SS     32
#define HWIMG  (HH*WW)          // 491520
#define NSLOT  61440            // 2*H*W/step^2
#define GXC    252
#define GYC    116
#define GG     (GXC*GYC)        // 29232
#define MARG   10
#define BB     240              // persistent grid: 240 blocks x 256 = NSLOT threads
#define TT     256
#define NWARP  (TT/32)          // 8
#define NCANDB 115              // ceil(GG / TT)
#define WPI    (HWIMG/32)       // 15360 bitmask words per step
#define NSUB   8
#define SUBQ   (BB/NSUB)        // 30

// Scratch (device globals; no allocations allowed)
__device__ __align__(16) unsigned char g_occ[2][GG];  // parity double-buffered; zero at load & exit
__device__ unsigned g_on[(SS-1)*WPI];                 // precomputed fwd-bwd consistency bitmask
__device__ int g_candList[GG];
__device__ int g_slotCnt[NWARP][BB];                  // free-slot count per (warp-row, block)
__device__ int g_nc;
struct __align__(128) PadCnt { unsigned v; unsigned pad[31]; };
__device__ PadCnt g_barSub[NSUB];
__device__ PadCnt g_barMaster;
__device__ __align__(128) volatile unsigned g_barGen;

__device__ __forceinline__ void gridbar() {
    __syncthreads();
    if (threadIdx.x == 0) {
        __threadfence();                       // release: publish this block's writes
        unsigned gen = g_barGen;               // read BEFORE arrival (else lost-release race)
        bool last = false;
        if (atomicAdd(&g_barSub[blockIdx.x & (NSUB - 1)].v, 1u) == SUBQ - 1u) {
            if (atomicAdd(&g_barMaster.v, 1u) == NSUB - 1u) last = true;
        }
        if (last) {
            g_barMaster.v = 0;
            #pragma unroll
            for (int i = 0; i < NSUB; i++) g_barSub[i].v = 0;
            __threadfence();
            g_barGen = gen + 1u;
        } else {
            while (g_barGen == gen) { }
        }
    }
    __syncthreads();
}

// ---- math helpers: byte-identical to R1..R7 (rel_err was 0.0) ----
__device__ __forceinline__ float bil4(float s00, float s01, float s10, float s11,
                                      float w00, float w01, float w10, float w11) {
    return fmaf(s11, w11, fmaf(s10, w10, fmaf(s00, w00, __fmul_rn(s01, w01))));
}

struct BilW {
    int ix0, ix1, iy0, iy1;
    float w00, w01, w10, w11;
};

__device__ __forceinline__ BilW mkw(float x, float y) {
    BilW b;
    float x0f = floorf(x), y0f = floorf(y);
    float wx1 = __fsub_rn(x, x0f); float wx0 = __fsub_rn(1.0f, wx1);
    float wy1 = __fsub_rn(y, y0f); float wy0 = __fsub_rn(1.0f, wy1);
    int ix0 = (int)x0f; ix0 = ix0 < 0 ? 0 : (ix0 > WW-1 ? WW-1 : ix0);
    int iy0 = (int)y0f; iy0 = iy0 < 0 ? 0 : (iy0 > HH-1 ? HH-1 : iy0);
    b.ix0 = ix0; b.ix1 = (ix0+1 > WW-1) ? WW-1 : ix0+1;
    b.iy0 = iy0; b.iy1 = (iy0+1 > HH-1) ? HH-1 : iy0+1;
    b.w00 = __fmul_rn(wy0, wx0); b.w01 = __fmul_rn(wy0, wx1);
    b.w10 = __fmul_rn(wy1, wx0); b.w11 = __fmul_rn(wy1, wx1);
    return b;
}

__device__ __forceinline__ float on_at(const float* __restrict__ fb0,
                                       const float* __restrict__ fb1,
                                       float a0, float a1, int py, int px) {
    float xt = __fadd_rn((float)px, a0);
    float yt = __fadd_rn((float)py, a1);
    BilW b = mkw(xt, yt);
    float f00 = fb0[b.iy0*WW+b.ix0], f01 = fb0[b.iy0*WW+b.ix1];
    float f10 = fb0[b.iy1*WW+b.ix0], f11 = fb0[b.iy1*WW+b.ix1];
    float g00 = fb1[b.iy0*WW+b.ix0], g01 = fb1[b.iy0*WW+b.ix1];
    float g10 = fb1[b.iy1*WW+b.ix0], g11 = fb1[b.iy1*WW+b.ix1];
    float f0 = bil4(f00, f01, f10, f11, b.w00, b.w01, b.w10, b.w11);
    float f1 = bil4(g00, g01, g10, g11, b.w00, b.w01, b.w10, b.w11);
    float d0 = __fadd_rn(a0, f0), d1 = __fadd_rn(a1, f1);
    float diff = __fsqrt_rn(fmaf(d1, d1, __fmul_rn(d0, d0)));
    float m1 = __fsqrt_rn(fmaf(a1, a1, __fmul_rn(a0, a0)));
    float m2 = __fsqrt_rn(fmaf(f1, f1, __fmul_rn(f0, f0)));
    float mag = __fmul_rn(0.5f, __fadd_rn(m1, m2));
    return (diff <= fmaf(0.01f, mag, 0.1f)) ? 1.0f : 0.0f;
}

// ---------------- precompute (R6 2-pixel version; R7's float4 variant regressed) ----------------
__global__ void __launch_bounds__(256) k_onmask(const float* __restrict__ ff,
                                                const float* __restrict__ fb) {
    int s = blockIdx.y;
    int p = blockIdx.x * 256 + threadIdx.x;        // first pixel
    int q = p + HWIMG/2;                           // second pixel (independent word)
    const float* ff0 = ff + (size_t)s * 2 * HWIMG;
    const float* ff1 = ff0 + HWIMG;
    const float* fb0 = fb + (size_t)s * 2 * HWIMG;
    const float* fb1 = fb0 + HWIMG;
    float a0 = ff0[p], a1 = ff1[p];
    float b0 = ff0[q], b1 = ff1[q];
    float on1 = on_at(fb0, fb1, a0, a1, p >> 10, p & 1023);
    float on2 = on_at(fb0, fb1, b0, b1, q >> 10, q & 1023);
    unsigned m1 = __ballot_sync(0xffffffffu, on1 != 0.0f);
    unsigned m2 = __ballot_sync(0xffffffffu, on2 != 0.0f);
    if ((threadIdx.x & 31) == 0) {
        g_on[s*WPI + (p >> 5)] = m1;
        g_on[s*WPI + (q >> 5)] = m2;
    }
}

// ---------------- persistent serial kernel, 2 grid barriers per step ----------------
// Slot ownership is warp-swizzled for load balance: thread (b, warp wi, lane) owns
// slot t = (b + BB*wi)*32 + lane. Ascending slot order == (wi, b, lane) lexicographic.
// Candidate/occ logic uses the independent linear id u = b*TT + tid.
__global__ void __launch_bounds__(TT, 2) k_linker(const float* __restrict__ ff,
                                                  float* __restrict__ out) {
    const int tid  = threadIdx.x;
    const int b    = blockIdx.x;
    const int lane = tid & 31;
    const int wid  = tid >> 5;
    const int t    = (b + BB*wid)*32 + lane;   // swizzled slot id
    const int u    = b * TT + tid;             // linear id (occ / candidates)

    float* X  = out;
    float* Y  = out + SS*NSLOT;
    float* St = out + 2*SS*NSLOT;

    __shared__ int sh_candBase, sh_nc_sh;
    __shared__ int sh_rowtot[NWARP], sh_c[NWARP];

    // ---- per-thread persistent state (slot t is touched ONLY by this thread) ----
    float myX, myY, mySt;
    {
        bool ing = t < GG;
        myX  = ing ? (float)(MARG + 4*(t % GXC)) : 0.0f;
        myY  = ing ? (float)(MARG + 4*(t / GXC)) : 0.0f;
        mySt = ing ? 0.0f : -1.0f;
        X[t] = myX; Y[t] = myY;            // row 0
    }

    for (int s = 0; s < SS - 1; s++) {
        const int par = s & 1;
        unsigned char* occ = g_occ[par];
        const float* ff0 = ff + (size_t)s * 2 * HWIMG;
        const float* ff1 = ff0 + HWIMG;
        const unsigned* onw = g_on + s*WPI;

        // ===== Phase A: clear idle occ buffer (own linear cell), advance own slot, mark occ =====
        if (u < GG) g_occ[par ^ 1][u] = 0;

        bool freeflag = true;                 // == (updated Start < 0)
        float xw = 0.0f, yw = 0.0f;
        if (mySt >= 0.0f) {
            BilW bw = mkw(myX, myY);
            float u00 = ff0[bw.iy0*WW+bw.ix0], u01 = ff0[bw.iy0*WW+bw.ix1];
            float u10 = ff0[bw.iy1*WW+bw.ix0], u11 = ff0[bw.iy1*WW+bw.ix1];
            float v00 = ff1[bw.iy0*WW+bw.ix0], v01 = ff1[bw.iy0*WW+bw.ix1];
            float v10 = ff1[bw.iy1*WW+bw.ix0], v11 = ff1[bw.iy1*WW+bw.ix1];
            float uvx = bil4(u00, u01, u10, u11, bw.w00, bw.w01, bw.w10, bw.w11);
            float uvy = bil4(v00, v01, v10, v11, bw.w00, bw.w01, bw.w10, bw.w11);
            float xt = __fadd_rn(myX, uvx);
            float yt = __fadd_rn(myY, uvy);
            bool marg = (xt > (float)MARG) && (yt > (float)MARG) &&
                        (xt < (float)(WW - MARG)) && (yt < (float)(HH - MARG));
            if (marg) {
                // bitmask probes reconstruct exactly 0.0f/1.0f (bit-identical to on_at)
                float on00 = (float)((onw[(bw.iy0<<5) + (bw.ix0>>5)] >> (bw.ix0&31)) & 1u);
                float on01 = (float)((onw[(bw.iy0<<5) + (bw.ix1>>5)] >> (bw.ix1&31)) & 1u);
                float on10 = (float)((onw[(bw.iy1<<5) + (bw.ix0>>5)] >> (bw.ix0&31)) & 1u);
                float on11 = (float)((onw[(bw.iy1<<5) + (bw.ix1>>5)] >> (bw.ix1&31)) & 1u);
                float onv = bil4(on00, on01, on10, on11, bw.w00, bw.w01, bw.w10, bw.w11);
                if (onv > 0.5f) {
                    freeflag = false;
                    xw = xt; yw = yt;
                    int oy = (int)yt, ox = (int)xt;
                    int iylo = (oy - 9) / 4; if (iylo < 0) iylo = 0;
                    int iyhi = (oy - 8) / 4; if (iyhi > GYC-1) iyhi = GYC-1;
                    int ixlo = (ox - 9) / 4; if (ixlo < 0) ixlo = 0;
                    int ixhi = (ox - 8) / 4; if (ixhi > GXC-1) ixhi = GXC-1;
                    for (int iy = iylo; iy <= iyhi; iy++)
                        for (int ix = ixlo; ix <= ixhi; ix++)
                            occ[iy*GXC + ix] = 1;          // idempotent
                }
            }
        }
        if (freeflag) mySt = -1.0f;
        myX = xw; myY = yw;
        X[(s+1)*NSLOT + t] = xw;
        Y[(s+1)*NSLOT + t] = yw;

        // per-(warp-row, block) free-slot count: one STG per warp, no shared/syncs
        unsigned amask = __ballot_sync(0xffffffffu, freeflag);
        if (lane == 0) g_slotCnt[wid][b] = __popc(amask);

        gridbar();   // occ marks + slot counts + row s+1 visible

        // ===== Phase B: slot ranking (swizzled order) + ordered candidate compaction =====
        if (tid == 0) sh_candBase = 0;
        __syncthreads();

        // each warp reduces its own row of g_slotCnt: total + prefix(b'<b)
        int rcnt = 0, rpre = 0;
        #pragma unroll
        for (int k = 0; k < 8; k++) {
            int i = lane + 32*k;
            if (i < BB) {
                int c = __ldcg(&g_slotCnt[wid][i]);
                rcnt += c;
                if (i < b) rpre += c;
            }
        }
        int rowtot = __reduce_add_sync(0xffffffffu, rcnt);
        int rowpre = __reduce_add_sync(0xffffffffu, rpre);
        if (lane == 0) sh_rowtot[wid] = rowtot;

        // candidates (linear id u)
        bool cf = false;
        unsigned cmask = 0;
        if (b < NCANDB) {
            if (u < GG) cf = (__ldcg(&occ[u]) == 0);
            // candidate base for this block: zeros in occ[0 .. b*TT)
            int pre = b * TT;
            int zbits = 0;
            for (int i = tid * 16; i < pre; i += TT * 16) {
                uint4 v = __ldcg((const uint4*)(occ + i));
                zbits += __popc(__vcmpeq4(v.x, 0u)) + __popc(__vcmpeq4(v.y, 0u))
                       + __popc(__vcmpeq4(v.z, 0u)) + __popc(__vcmpeq4(v.w, 0u));
            }
            zbits = __reduce_add_sync(0xffffffffu, zbits);
            if (lane == 0 && zbits) atomicAdd(&sh_candBase, zbits >> 3);
            cmask = __ballot_sync(0xffffffffu, cf);
            if (lane == 0) sh_c[wid] = __popc(cmask);
        }
        __syncthreads();
        if (tid == 0) {
            if (b < NCANDB) {
                int crun = sh_candBase;
                #pragma unroll
                for (int i = 0; i < NWARP; i++) { int c = sh_c[i]; sh_c[i] = crun; crun += c; }
                if (b == NCANDB - 1) g_nc = crun;     // total free candidates
            }
            int nfr = 0;
            #pragma unroll
            for (int i = 0; i < NWARP; i++) nfr += sh_rowtot[i];
            sh_nc_sh = nfr;                            // reuse as nf broadcast
        }
        __syncthreads();
        int base = rowpre;
        #pragma unroll
        for (int i = 0; i < NWARP; i++) if (i < wid) base += sh_rowtot[i];
        int myrank = freeflag ? base + __popc(amask & ((1u << lane) - 1u)) : -1;
        if (cf)
            g_candList[sh_c[wid] + __popc(cmask & ((1u << lane) - 1u))] = u;
        int nf = sh_nc_sh;

        gridbar();   // candList + g_nc visible

        // ===== Phase C: self-birth (k-th free slot takes k-th free candidate) =====
        int nc = __ldcg(&g_nc);
        int m = nf < nc ? nf : nc;
        if (myrank >= 0 && myrank < m) {
            int g = __ldcg(&g_candList[myrank]);
            int iy = g / GXC, ix = g - iy * GXC;
            myX = (float)(MARG + 4*ix);
            myY = (float)(MARG + 4*iy);
            mySt = (float)(s + 1);
            X[(s+1)*NSLOT + t] = myX;
            Y[(s+1)*NSLOT + t] = myY;
        }
        // no barrier: next Phase A reads only thread-own state (bar2 separates occ/list reuse)
    }

    St[t] = mySt;
    if (u < GG) g_occ[0][u] = 0;   // last step used buffer 0; restore zero-invariant for replay
}

extern "C" void kernel_launch(void* const* d_in, const int* in_sizes, int n_in,
                              void* d_out, int out_size) {
    (void)in_sizes; (void)n_in; (void)out_size;
    const float* ff = (const float*)d_in[0];
    const float* fb = (const float*)d_in[1];
    float* out = (float*)d_out;
    dim3 g1(HWIMG/512, SS-1);
    k_onmask<<<g1, 256>>>(ff, fb);
    k_linker<<<BB, TT>>>(ff, out);
}

// round 9
// speedup vs baseline: 2.2247x; 1.3087x over previous
#include <cuda_runtime.h>

// Problem constants (fixed by setup_inputs: H=480, W=1024, S=32, margin=10, step=4)
#define HH     480
#define WW     1024
#define SS     32
#define HWIMG  (HH*WW)          // 491520
#define NSLOT  61440            // 2*H*W/step^2
#define GXC    252
#define GYC    116
#define GG     (GXC*GYC)        // 29232
#define MARG   10
#define BB     240              // persistent grid: 240 blocks x 256 = NSLOT threads
#define TT     256
#define NWARP  (TT/32)          // 8
#define WPI    (HWIMG/32)       // 15360 bitmask words per step
#define WPR    8                // occupancy words per grid row (256 bits >= GXC)
#define PWORDS 1024             // padded occupancy words (>= GYC*WPR = 928)
#define NSUB   8
#define SUBQ   (BB/NSUB)        // 30

// Scratch (device globals; no allocations allowed)
// Occupancy as BITMASK, 3-buffer rotation: A(s) marks buf(s%3), clears buf((s+2)%3);
// B'(s) reads buf(s%3). All pairs barrier-separated (one barrier per step, after A).
__device__ __align__(16) unsigned g_bits[3][PWORDS];
__device__ unsigned g_on[(SS-1)*WPI];                 // precomputed fwd-bwd consistency bitmask
__device__ int g_slotCnt[2][NWARP][BB];               // parity-buffered (warp-row, block) free counts
struct __align__(128) PadCnt { unsigned v; unsigned pad[31]; };
__device__ PadCnt g_barSub[NSUB];
__device__ PadCnt g_barMaster;
__device__ __align__(128) volatile unsigned g_barGen;

// empty pattern: pad bits (ix>=252 in-row, rows>=GYC) are permanently "occupied"
__device__ __forceinline__ unsigned epat(int w) {
    return (w >= GYC*WPR) ? 0xFFFFFFFFu : (((w & 7) == 7) ? 0xF0000000u : 0u);
}

__device__ __forceinline__ void gridbar() {
    __syncthreads();
    if (threadIdx.x == 0) {
        __threadfence();                       // release: publish this block's writes
        unsigned gen = g_barGen;               // read BEFORE arrival (else lost-release race)
        bool last = false;
        if (atomicAdd(&g_barSub[blockIdx.x & (NSUB - 1)].v, 1u) == SUBQ - 1u) {
            if (atomicAdd(&g_barMaster.v, 1u) == NSUB - 1u) last = true;
        }
        if (last) {
            g_barMaster.v = 0;
            #pragma unroll
            for (int i = 0; i < NSUB; i++) g_barSub[i].v = 0;
            __threadfence();
            g_barGen = gen + 1u;
        } else {
            while (g_barGen == gen) { }
        }
    }
    __syncthreads();
}

// ---- math helpers: byte-identical to R1..R8 (rel_err was 0.0) ----
__device__ __forceinline__ float bil4(float s00, float s01, float s10, float s11,
                                      float w00, float w01, float w10, float w11) {
    return fmaf(s11, w11, fmaf(s10, w10, fmaf(s00, w00, __fmul_rn(s01, w01))));
}

struct BilW {
    int ix0, ix1, iy0, iy1;
    float w00, w01, w10, w11;
};

__device__ __forceinline__ BilW mkw(float x, float y) {
    BilW b;
    float x0f = floorf(x), y0f = floorf(y);
    float wx1 = __fsub_rn(x, x0f); float wx0 = __fsub_rn(1.0f, wx1);
    float wy1 = __fsub_rn(y, y0f); float wy0 = __fsub_rn(1.0f, wy1);
    int ix0 = (int)x0f; ix0 = ix0 < 0 ? 0 : (ix0 > WW-1 ? WW-1 : ix0);
    int iy0 = (int)y0f; iy0 = iy0 < 0 ? 0 : (iy0 > HH-1 ? HH-1 : iy0);
    b.ix0 = ix0; b.ix1 = (ix0+1 > WW-1) ? WW-1 : ix0+1;
    b.iy0 = iy0; b.iy1 = (iy0+1 > HH-1) ? HH-1 : iy0+1;
    b.w00 = __fmul_rn(wy0, wx0); b.w01 = __fmul_rn(wy0, wx1);
    b.w10 = __fmul_rn(wy1, wx0); b.w11 = __fmul_rn(wy1, wx1);
    return b;
}

__device__ __forceinline__ float on_at(const float* __restrict__ fb0,
                                       const float* __restrict__ fb1,
                                       float a0, float a1, int py, int px) {
    float xt = __fadd_rn((float)px, a0);
    float yt = __fadd_rn((float)py, a1);
    BilW b = mkw(xt, yt);
    float f00 = fb0[b.iy0*WW+b.ix0], f01 = fb0[b.iy0*WW+b.ix1];
    float f10 = fb0[b.iy1*WW+b.ix0], f11 = fb0[b.iy1*WW+b.ix1];
    float g00 = fb1[b.iy0*WW+b.ix0], g01 = fb1[b.iy0*WW+b.ix1];
    float g10 = fb1[b.iy1*WW+b.ix0], g11 = fb1[b.iy1*WW+b.ix1];
    float f0 = bil4(f00, f01, f10, f11, b.w00, b.w01, b.w10, b.w11);
    float f1 = bil4(g00, g01, g10, g11, b.w00, b.w01, b.w10, b.w11);
    float d0 = __fadd_rn(a0, f0), d1 = __fadd_rn(a1, f1);
    float diff = __fsqrt_rn(fmaf(d1, d1, __fmul_rn(d0, d0)));
    float m1 = __fsqrt_rn(fmaf(a1, a1, __fmul_rn(a0, a0)));
    float m2 = __fsqrt_rn(fmaf(f1, f1, __fmul_rn(f0, f0)));
    float mag = __fmul_rn(0.5f, __fadd_rn(m1, m2));
    return (diff <= fmaf(0.01f, mag, 0.1f)) ? 1.0f : 0.0f;
}

// ---------------- precompute (R6 2-pixel version) ----------------
__global__ void __launch_bounds__(256) k_onmask(const float* __restrict__ ff,
                                                const float* __restrict__ fb) {
    int s = blockIdx.y;
    int p = blockIdx.x * 256 + threadIdx.x;
    int q = p + HWIMG/2;
    const float* ff0 = ff + (size_t)s * 2 * HWIMG;
    const float* ff1 = ff0 + HWIMG;
    const float* fb0 = fb + (size_t)s * 2 * HWIMG;
    const float* fb1 = fb0 + HWIMG;
    float a0 = ff0[p], a1 = ff1[p];
    float b0 = ff0[q], b1 = ff1[q];
    float on1 = on_at(fb0, fb1, a0, a1, p >> 10, p & 1023);
    float on2 = on_at(fb0, fb1, b0, b1, q >> 10, q & 1023);
    unsigned m1 = __ballot_sync(0xffffffffu, on1 != 0.0f);
    unsigned m2 = __ballot_sync(0xffffffffu, on2 != 0.0f);
    if ((threadIdx.x & 31) == 0) {
        g_on[s*WPI + (p >> 5)] = m1;
        g_on[s*WPI + (q >> 5)] = m2;
    }
}

// ---------------- persistent serial kernel, ONE grid barrier per step ----------------
// Slot ownership warp-swizzled (R8): thread (b, warp wi, lane) owns slot
// t = (b + BB*wi)*32 + lane; ascending slot order == (wi, b, lane).
__global__ void __launch_bounds__(TT, 2) k_linker(const float* __restrict__ ff,
                                                  float* __restrict__ out) {
    const int tid  = threadIdx.x;
    const int b    = blockIdx.x;
    const int lane = tid & 31;
    const int wid  = tid >> 5;
    const int t    = (b + BB*wid)*32 + lane;   // swizzled slot id

    float* X  = out;
    float* Y  = out + SS*NSLOT;
    float* St = out + 2*SS*NSLOT;

    __shared__ unsigned sh_bits[PWORDS];       // 4KB: full occupancy snapshot
    __shared__ int sh_pre[TT];                 // exclusive zero-count prefix per 4-word chunk
    __shared__ int sh_rowtot[NWARP], sh_wsum[NWARP], sh_woff[NWARP];
    __shared__ int sh_nf, sh_nc;

    // ---- init: per-thread persistent state + all 3 occupancy buffers to empty pattern ----
    float myX, myY, mySt;
    {
        bool ing = t < GG;
        myX  = ing ? (float)(MARG + 4*(t % GXC)) : 0.0f;
        myY  = ing ? (float)(MARG + 4*(t / GXC)) : 0.0f;
        mySt = ing ? 0.0f : -1.0f;
        X[t] = myX; Y[t] = myY;            // row 0
    }
    if (b < 12) {                           // 12 blocks x 256 = 3072 = 3*PWORDS
        int w = (b >> 2) * 0 + ((b & 3) << 8) + tid;   // word within buffer
        g_bits[b >> 2][w] = epat(w);
    }
    gridbar();   // occupancy init visible before A(0) marks

    for (int s = 0; s < SS - 1; s++) {
        const int par = s & 1;
        unsigned* bm = g_bits[s % 3];                  // marked here, read in B'(s)
        unsigned* bc = g_bits[(s + 2) % 3];            // cleared here (marked at A(s+2))
        const float* ff0 = ff + (size_t)s * 2 * HWIMG;
        const float* ff1 = ff0 + HWIMG;
        const unsigned* onw = g_on + s*WPI;

        // ===== Phase A: clear future buffer, advance own slot, mark occupancy bits =====
        if (b < 4) { int w = (b << 8) + tid; bc[w] = epat(w); }

        bool freeflag = true;                 // == (updated Start < 0)
        float xw = 0.0f, yw = 0.0f;
        if (mySt >= 0.0f) {
            BilW bw = mkw(myX, myY);
            float u00 = ff0[bw.iy0*WW+bw.ix0], u01 = ff0[bw.iy0*WW+bw.ix1];
            float u10 = ff0[bw.iy1*WW+bw.ix0], u11 = ff0[bw.iy1*WW+bw.ix1];
            float v00 = ff1[bw.iy0*WW+bw.ix0], v01 = ff1[bw.iy0*WW+bw.ix1];
            float v10 = ff1[bw.iy1*WW+bw.ix0], v11 = ff1[bw.iy1*WW+bw.ix1];
            float uvx = bil4(u00, u01, u10, u11, bw.w00, bw.w01, bw.w10, bw.w11);
            float uvy = bil4(v00, v01, v10, v11, bw.w00, bw.w01, bw.w10, bw.w11);
            float xt = __fadd_rn(myX, uvx);
            float yt = __fadd_rn(myY, uvy);
            bool marg = (xt > (float)MARG) && (yt > (float)MARG) &&
                        (xt < (float)(WW - MARG)) && (yt < (float)(HH - MARG));
            if (marg) {
                // bitmask probes reconstruct exactly 0.0f/1.0f (bit-identical to on_at)
                float on00 = (float)((onw[(bw.iy0<<5) + (bw.ix0>>5)] >> (bw.ix0&31)) & 1u);
                float on01 = (float)((onw[(bw.iy0<<5) + (bw.ix1>>5)] >> (bw.ix1&31)) & 1u);
                float on10 = (float)((onw[(bw.iy1<<5) + (bw.ix0>>5)] >> (bw.ix0&31)) & 1u);
                float on11 = (float)((onw[(bw.iy1<<5) + (bw.ix1>>5)] >> (bw.ix1&31)) & 1u);
                float onv = bil4(on00, on01, on10, on11, bw.w00, bw.w01, bw.w10, bw.w11);
                if (onv > 0.5f) {
                    freeflag = false;
                    xw = xt; yw = yt;
                    int oy = (int)yt, ox = (int)xt;
                    int iylo = (oy - 9) / 4; if (iylo < 0) iylo = 0;
                    int iyhi = (oy - 8) / 4; if (iyhi > GYC-1) iyhi = GYC-1;
                    int ixlo = (ox - 9) / 4; if (ixlo < 0) ixlo = 0;
                    int ixhi = (ox - 8) / 4; if (ixhi > GXC-1) ixhi = GXC-1;
                    // mark cells [iylo..iyhi] x [ixlo..ixhi] (<=2 rows, <=2 bits/row) via RED.OR
                    for (int iy = iylo; iy <= iyhi; iy++) {
                        int w = (iy << 3) + (ixlo >> 5);
                        unsigned m1 = 1u << (ixlo & 31);
                        if (ixhi > ixlo) {
                            if ((ixlo & 31) == 31) {
                                atomicOr(&bm[w], m1);
                                atomicOr(&bm[w + 1], 1u);
                            } else {
                                atomicOr(&bm[w], m1 | (m1 << 1));
                            }
                        } else {
                            atomicOr(&bm[w], m1);
                        }
                    }
                }
            }
        }
        if (freeflag) mySt = -1.0f;
        myX = xw; myY = yw;
        X[(s+1)*NSLOT + t] = xw;
        Y[(s+1)*NSLOT + t] = yw;

        unsigned amask = __ballot_sync(0xffffffffu, freeflag);
        if (lane == 0) g_slotCnt[par][wid][b] = __popc(amask);

        gridbar();   // occupancy marks + slot counts + row s+1 visible

        // ===== Phase B': full-map snapshot + local scan + slot ranking + self-birth =====
        // each thread ingests 4 words (whole 4KB map per block)
        uint4 v = __ldcg((const uint4*)bm + tid);
        sh_bits[tid*4 + 0] = v.x; sh_bits[tid*4 + 1] = v.y;
        sh_bits[tid*4 + 2] = v.z; sh_bits[tid*4 + 3] = v.w;
        int zc = 128 - (__popc(v.x) + __popc(v.y) + __popc(v.z) + __popc(v.w));

        // block exclusive scan of per-chunk zero counts
        int inc = zc;
        #pragma unroll
        for (int d = 1; d < 32; d <<= 1) {
            int n = __shfl_up_sync(0xffffffffu, inc, d);
            if (lane >= d) inc += n;
        }
        if (lane == 31) sh_wsum[wid] = inc;

        // slot ranking: each warp reduces its row of slotCnt (total + prefix b'<b)
        int rcnt = 0, rpre = 0;
        #pragma unroll
        for (int k = 0; k < 8; k++) {
            int i = lane + 32*k;
            if (i < BB) {
                int c = __ldcg(&g_slotCnt[par][wid][i]);
                rcnt += c;
                if (i < b) rpre += c;
            }
        }
        int rowtot = __reduce_add_sync(0xffffffffu, rcnt);
        int rowpre = __reduce_add_sync(0xffffffffu, rpre);
        if (lane == 0) sh_rowtot[wid] = rowtot;
        __syncthreads();
        if (tid == 0) {
            int run = 0;
            #pragma unroll
            for (int i = 0; i < NWARP; i++) { int c = sh_wsum[i]; sh_woff[i] = run; run += c; }
            sh_nc = run;                               // total free candidates (identical in all blocks)
            int nfr = 0;
            #pragma unroll
            for (int i = 0; i < NWARP; i++) nfr += sh_rowtot[i];
            sh_nf = nfr;
        }
        __syncthreads();
        sh_pre[tid] = sh_woff[wid] + inc - zc;         // exclusive chunk prefix
        int base = rowpre;
        #pragma unroll
        for (int i = 0; i < NWARP; i++) if (i < wid) base += sh_rowtot[i];
        int myrank = freeflag ? base + __popc(amask & ((1u << lane) - 1u)) : -1;
        __syncthreads();

        // self-birth: k-th free slot takes the k-th zero bit (= k-th free candidate)
        int m = sh_nf < sh_nc ? sh_nf : sh_nc;
        if (myrank >= 0 && myrank < m) {
            int r = myrank;
            int lo = 0, hi = TT - 1;
            while (lo < hi) {                          // last chunk with prefix <= r
                int mid = (lo + hi + 1) >> 1;
                if (sh_pre[mid] <= r) lo = mid; else hi = mid - 1;
            }
            int k = r - sh_pre[lo];
            int wsel = -1, bit = 0;
            #pragma unroll
            for (int j = 0; j < 4; j++) {
                unsigned zw = ~sh_bits[lo*4 + j];
                int nz = __popc(zw);
                if (wsel < 0) {
                    if (k < nz) { wsel = lo*4 + j; bit = __fns(zw, 0, k + 1); }
                    else k -= nz;
                }
            }
            int iy = wsel >> 3;
            int ix = ((wsel & 7) << 5) | bit;
            myX = (float)(MARG + 4*ix);
            myY = (float)(MARG + 4*iy);
            mySt = (float)(s + 1);
            X[(s+1)*NSLOT + t] = myX;
            Y[(s+1)*NSLOT + t] = myY;
        }
        // no second barrier: everything phase C needed was block-local.
    }

    St[t] = mySt;
}

extern "C" void kernel_launch(void* const* d_in, const int* in_sizes, int n_in,
                              void* d_out, int out_size) {
    (void)in_sizes; (void)n_in; (void)out_size;
    const float* ff = (const float*)d_in[0];
    const float* fb = (const float*)d_in[1];
    float* out = (float*)d_out;
    dim3 g1(HWIMG/512, SS-1);
    k_onmask<<<g1, 256>>>(ff, fb);
    k_linker<<<BB, TT>>>(ff, out);
}